// round 14
// baseline (speedup 1.0000x reference)
#include <cuda_runtime.h>

// ---------------------------------------------------------------------------
// OTPE single timestep — overlapped-phase structure.
//  K1': heterogeneous grid = GEMV blocks (every 33rd) + E-update blocks.
//       Mixes the read-only W stream with E read/write traffic so phase 1
//       runs at the mixed-stream bandwidth (~7.25TB/s) instead of the
//       read-only cap (~5.4TB/s).
//  K2 : fused deterministic reduce + LIF post (PDL).
//  K3': R_new = sig*R_hat + sg*E_new, re-reading E_new (partially L2-hot).
// Inputs: x[8192], W[8192,4096], u[4096], E[8192,4096], R_hat[8192,4096],
//         g_bar[4096], ratio[1]
// Output: s, u_new, E_new, R_new, g_bar_new, ratio_new
// ---------------------------------------------------------------------------

#define N_IN   8192
#define N_OUT  4096
#define N_OUTV (N_OUT / 4)               // 1024 float4 per row
// sigmoid(2.0) in fp32
#define SIG_TAU 0.88079707797788231f

#define NSPLIT 256
#define ROWS_PER_SPLIT (N_IN / NSPLIT)     // 32
#define GEMV_STAGES 8

#define NVEC  (N_IN * (long long)N_OUT / 4)   // 8388608 float4
#define NEBLK 32768                            // E-update blocks (1 f4/thread)
#define NGBLK 1024                             // GEMV blocks
#define NTOT  (NEBLK + NGBLK)                  // 33792 = 33 * 1024

// scratch (device globals; no allocation allowed)
__device__ __align__(16) float g_part[NSPLIT * N_OUT];    // 4 MB
__device__ __align__(16) float g_sg[N_OUT];

// ---------------------------------------------------------------------------
// K1': 1D grid 33792, block 256. bid%33==0 -> GEMV role (gidx=bid/33,
// 4 col-blocks x 256 splits); else E-update role (eidx dense 0..32767).
// Interleaving keeps W reads and E read/write co-resident every wave.
// ---------------------------------------------------------------------------
__global__ void __launch_bounds__(256)
otpe_phase1(const float4* __restrict__ W4, const float* __restrict__ x,
            const float4* __restrict__ E, float4* __restrict__ Eo) {
    __shared__ __align__(16) float4 tile[GEMV_STAGES][256];
    __shared__ float sx[ROWS_PER_SPLIT];

    const int bid = blockIdx.x;
    const int q   = bid / 33;
    const int t   = threadIdx.x;

    if (bid - q * 33 == 0) {
        // ---------------- GEMV role (R8 cp.async pipeline) ----------------
        const int split = q >> 2;                 // 0..255
        const int colv  = (q & 3) * 256 + t;      // 0..1023
        const int r0    = split * ROWS_PER_SPLIT;

        if (t < ROWS_PER_SPLIT)
            sx[t] = x[r0 + t];
        __syncthreads();

        const float4* Wg = W4 + (size_t)r0 * N_OUTV + colv;

#pragma unroll
        for (int s = 0; s < GEMV_STAGES; ++s) {
            unsigned dst = (unsigned)__cvta_generic_to_shared(&tile[s][t]);
            asm volatile("cp.async.cg.shared.global [%0], [%1], 16;\n"
                         :: "r"(dst), "l"(Wg + (size_t)s * N_OUTV));
            asm volatile("cp.async.commit_group;\n");
        }

        float4 A = make_float4(0.f, 0.f, 0.f, 0.f);
#pragma unroll
        for (int r = 0; r < ROWS_PER_SPLIT; ++r) {
            asm volatile("cp.async.wait_group %0;\n"
                         :: "n"(GEMV_STAGES - 1) : "memory");
            const float4 w  = tile[r & (GEMV_STAGES - 1)][t];
            const float  xr = sx[r];
            A.x = fmaf(xr, w.x, A.x);
            A.y = fmaf(xr, w.y, A.y);
            A.z = fmaf(xr, w.z, A.z);
            A.w = fmaf(xr, w.w, A.w);

            const int rn = r + GEMV_STAGES;
            if (rn < ROWS_PER_SPLIT) {
                unsigned dst = (unsigned)__cvta_generic_to_shared(
                    &tile[r & (GEMV_STAGES - 1)][t]);
                asm volatile("cp.async.cg.shared.global [%0], [%1], 16;\n"
                             :: "r"(dst), "l"(Wg + (size_t)rn * N_OUTV));
            }
            asm volatile("cp.async.commit_group;\n");
        }

        reinterpret_cast<float4*>(g_part)[(size_t)split * N_OUTV + colv] = A;
    } else {
        // ---------------- E-update role: E_new = sig*E + x ----------------
        const int eidx = bid - q - 1;             // dense 0..NEBLK-1
        const long long v = (long long)eidx * 256 + t;
        const int row = (int)(v >> 10);           // 1024 float4 per row

        const float  xi = __ldg(&x[row]);
        const float4 e  = E[v];

        float4 eo;
        eo.x = fmaf(SIG_TAU, e.x, xi);
        eo.y = fmaf(SIG_TAU, e.y, xi);
        eo.z = fmaf(SIG_TAU, e.z, xi);
        eo.w = fmaf(SIG_TAU, e.w, xi);

        Eo[v] = eo;
    }
}

// ---------------------------------------------------------------------------
// K2: fused reduce (256 splits) + per-column post. grid 64, block 256.
// PDL secondary: prefetch u/g_bar/ratio, wait on K1', read g_part.
// ---------------------------------------------------------------------------
__global__ void __launch_bounds__(256)
otpe_reduce_post(const float* __restrict__ u,
                 const float* __restrict__ g_bar,
                 const float* __restrict__ ratio,
                 float* __restrict__ out_s,
                 float* __restrict__ out_u,
                 float* __restrict__ out_gbar,
                 float* __restrict__ out_ratio) {
    __shared__ float sums[4][64];

    const int c   = threadIdx.x & 63;        // column within block
    const int k   = threadIdx.x >> 6;        // split group 0..3
    const int col = blockIdx.x * 64 + c;
    const int s0  = k * 64;
    const int j   = blockIdx.x * 64 + threadIdx.x;   // valid if tid<64

    float u_j = 0.f, gb_j = 0.f, ratio_in = 0.f;
    if (threadIdx.x < 64) {
        u_j      = u[j];
        gb_j     = g_bar[j];
        ratio_in = ratio[0];
    }

    cudaGridDependencySynchronize();   // K1's g_part now visible

    float a0 = 0.f, a1 = 0.f, a2 = 0.f, a3 = 0.f;
#pragma unroll
    for (int s = 0; s < 64; s += 4) {
        a0 += g_part[(size_t)(s0 + s + 0) * N_OUT + col];
        a1 += g_part[(size_t)(s0 + s + 1) * N_OUT + col];
        a2 += g_part[(size_t)(s0 + s + 2) * N_OUT + col];
        a3 += g_part[(size_t)(s0 + s + 3) * N_OUT + col];
    }
    sums[k][c] = (a0 + a1) + (a2 + a3);
    __syncthreads();

    if (threadIdx.x < 64) {
        const float u_pre = fmaf(SIG_TAU, u_j,
            ((sums[0][threadIdx.x] + sums[1][threadIdx.x]) +
             (sums[2][threadIdx.x] + sums[3][threadIdx.x])));

        const float spike = (u_pre >= 1.0f) ? 1.0f : 0.0f;
        const float t  = fmaf(10.0f, fabsf(u_pre - 1.0f), 1.0f);
        const float sg = 1.0f / (t * t);

        g_sg[j]  = sg;
        out_s[j] = spike;
        out_u[j] = u_pre - spike;          // soft reset (V_TH = 1)

        const float r0        = SIG_TAU * ratio_in;
        const float ratio_new = r0 + 1.0f;
        const float r         = r0 / ratio_new;
        // ds_du_prev / sig_tau == sg
        out_gbar[j] = fmaf(r, gb_j, (1.0f - r) * sg);

        if (j == 0) out_ratio[0] = ratio_new;
    }
}

// ---------------------------------------------------------------------------
// K3': R_new = sig*R_hat + sg*E_new. Reads E_new (written in K1', partially
// L2-resident) + R_hat, writes R_new. grid 32768, block 256.
// PDL secondary: prefetch E_new/R_hat (final since K1' completed before K2's
// trigger) before waiting on K2; read g_sg after.
// Math identical to R8: ro = sg*eo + sig*rr with the same fp32 eo.
// ---------------------------------------------------------------------------
__global__ void __launch_bounds__(256)
otpe_r_update(const float4* __restrict__ Eo,
              const float4* __restrict__ R,
              float4* __restrict__ Ro) {
    const long long v = (long long)blockIdx.x * 256 + threadIdx.x;
    const int colv = (int)(v & 1023);

    // dependency-free prefetch (K1' finished before K2 triggered us)
    const float4 eo = Eo[v];
    const float4 rr = R[v];

    cudaGridDependencySynchronize();   // K2's g_sg now visible

    const float4 sg4 = reinterpret_cast<const float4*>(g_sg)[colv];

    float4 ro;
    ro.x = fmaf(sg4.x, eo.x, SIG_TAU * rr.x);
    ro.y = fmaf(sg4.y, eo.y, SIG_TAU * rr.y);
    ro.z = fmaf(sg4.z, eo.z, SIG_TAU * rr.z);
    ro.w = fmaf(sg4.w, eo.w, SIG_TAU * rr.w);

    Ro[v] = ro;
}

// ---------------------------------------------------------------------------
extern "C" void kernel_launch(void* const* d_in, const int* in_sizes, int n_in,
                              void* d_out, int out_size) {
    const float* x     = (const float*)d_in[0];
    const float* W     = (const float*)d_in[1];
    const float* u     = (const float*)d_in[2];
    const float* E     = (const float*)d_in[3];
    const float* R     = (const float*)d_in[4];
    const float* g_bar = (const float*)d_in[5];
    const float* ratio = (const float*)d_in[6];

    float* out       = (float*)d_out;
    float* out_s     = out;
    float* out_u     = out + N_OUT;
    float* out_E     = out + 2 * N_OUT;
    float* out_R     = out_E + (size_t)N_IN * N_OUT;
    float* out_gbar  = out_R + (size_t)N_IN * N_OUT;
    float* out_ratio = out_gbar + N_OUT;

    // K1': heterogeneous GEMV + E-update grid (normal launch)
    otpe_phase1<<<NTOT, 256>>>((const float4*)W, x,
                               (const float4*)E, (float4*)out_E);

    // K2, K3': programmatic dependent launches, implicit completion triggers
    // (R9/R10: every early-trigger variant regresses).
    cudaLaunchAttribute pdl[1];
    pdl[0].id = cudaLaunchAttributeProgrammaticStreamSerialization;
    pdl[0].val.programmaticStreamSerializationAllowed = 1;

    {
        cudaLaunchConfig_t cfg = {};
        cfg.gridDim  = dim3(N_OUT / 64);
        cfg.blockDim = dim3(256);
        cfg.stream   = 0;
        cfg.attrs    = pdl;
        cfg.numAttrs = 1;
        cudaLaunchKernelEx(&cfg, otpe_reduce_post, u, g_bar, ratio,
                           out_s, out_u, out_gbar, out_ratio);
    }
    {
        cudaLaunchConfig_t cfg = {};
        cfg.gridDim  = dim3(NEBLK);
        cfg.blockDim = dim3(256);
        cfg.stream   = 0;
        cfg.attrs    = pdl;
        cfg.numAttrs = 1;
        cudaLaunchKernelEx(&cfg, otpe_r_update,
                           (const float4*)out_E, (const float4*)R,
                           (float4*)out_R);
    }
}

// round 15
// speedup vs baseline: 1.1844x; 1.1844x over previous
#include <cuda_runtime.h>

// ---------------------------------------------------------------------------
// OTPE single timestep — FINAL converged configuration (R8).
// Inputs (metadata order): x[8192], W[8192,4096], u[4096], E[8192,4096],
//                          R_hat[8192,4096], g_bar[4096], ratio[1]
// Output (flattened tuple): s[4096], u_new[4096], E_new[8192*4096],
//                           R_new[8192*4096], g_bar_new[4096], ratio_new[1]
//
// K1: split-K GEMV, cp.async 8-stage pipeline (read-stream cap ~5.4TB/s).
// K2: fused deterministic reduce + LIF post (PDL, prefetch-then-sync).
// K3: fused E/R elementwise, float4 1/thread (~82% DRAM; PDL).
// R_new identity: sg*(sig*E + x) = ds_du_prev*E + x*sg = sg*E_new.
// Measured dead ends (do not revisit): early PDL triggers, __ldcs/__stcs,
// K3 multi-elem ILP, device-gate K2+K3 fusion, GEMV/E-update phase overlap.
// ---------------------------------------------------------------------------

#define N_IN   8192
#define N_OUT  4096
#define N_OUTV (N_OUT / 4)               // 1024 float4 per row
// sigmoid(2.0) in fp32
#define SIG_TAU 0.88079707797788231f

#define NSPLIT 256
#define ROWS_PER_SPLIT (N_IN / NSPLIT)     // 32

#define GEMV_STAGES 8

// scratch (device globals; no allocation allowed)
__device__ __align__(16) float g_part[NSPLIT * N_OUT];    // 4 MB
__device__ __align__(16) float g_sg[N_OUT];

// ---------------------------------------------------------------------------
// K1: split-K GEMV via cp.async (LDGSTS .cg) 8-stage pipeline.
// grid (4, 256) = 1024 blocks, block 256, 32KB smem. Thread t stages and
// consumes only its own float4 column -> no __syncthreads in the mainloop.
// ---------------------------------------------------------------------------
__global__ void __launch_bounds__(256)
otpe_gemv_partial(const float4* __restrict__ W4, const float* __restrict__ x) {
    __shared__ __align__(16) float4 tile[GEMV_STAGES][256];
    __shared__ float sx[ROWS_PER_SPLIT];

    const int t     = threadIdx.x;
    const int split = blockIdx.y;
    const int r0    = split * ROWS_PER_SPLIT;
    const int colv  = blockIdx.x * 256 + t;

    if (t < ROWS_PER_SPLIT)
        sx[t] = x[r0 + t];
    __syncthreads();

    const float4* Wg = W4 + (size_t)r0 * N_OUTV + colv;

#pragma unroll
    for (int s = 0; s < GEMV_STAGES; ++s) {
        unsigned dst = (unsigned)__cvta_generic_to_shared(&tile[s][t]);
        asm volatile("cp.async.cg.shared.global [%0], [%1], 16;\n"
                     :: "r"(dst), "l"(Wg + (size_t)s * N_OUTV));
        asm volatile("cp.async.commit_group;\n");
    }

    float4 A = make_float4(0.f, 0.f, 0.f, 0.f);
#pragma unroll
    for (int r = 0; r < ROWS_PER_SPLIT; ++r) {
        asm volatile("cp.async.wait_group %0;\n" :: "n"(GEMV_STAGES - 1) : "memory");
        const float4 w  = tile[r & (GEMV_STAGES - 1)][t];
        const float  xr = sx[r];
        A.x = fmaf(xr, w.x, A.x);
        A.y = fmaf(xr, w.y, A.y);
        A.z = fmaf(xr, w.z, A.z);
        A.w = fmaf(xr, w.w, A.w);

        const int rn = r + GEMV_STAGES;
        if (rn < ROWS_PER_SPLIT) {
            unsigned dst = (unsigned)__cvta_generic_to_shared(
                &tile[r & (GEMV_STAGES - 1)][t]);
            asm volatile("cp.async.cg.shared.global [%0], [%1], 16;\n"
                         :: "r"(dst), "l"(Wg + (size_t)rn * N_OUTV));
        }
        asm volatile("cp.async.commit_group;\n");
    }

    reinterpret_cast<float4*>(g_part)[(size_t)split * N_OUTV + colv] = A;
}

// ---------------------------------------------------------------------------
// K2: fused reduce (256 splits) + per-column post. grid 64, block 256.
// PDL secondary: prefetch u/g_bar/ratio, THEN wait on K1, THEN read g_part.
// Fixed-order smem combine keeps the reduction deterministic.
// ---------------------------------------------------------------------------
__global__ void __launch_bounds__(256)
otpe_reduce_post(const float* __restrict__ u,
                 const float* __restrict__ g_bar,
                 const float* __restrict__ ratio,
                 float* __restrict__ out_s,
                 float* __restrict__ out_u,
                 float* __restrict__ out_gbar,
                 float* __restrict__ out_ratio) {
    __shared__ float sums[4][64];

    const int c   = threadIdx.x & 63;        // column within block
    const int k   = threadIdx.x >> 6;        // split group 0..3
    const int col = blockIdx.x * 64 + c;
    const int s0  = k * 64;
    const int j   = blockIdx.x * 64 + threadIdx.x;   // valid if tid<64

    // dependency-free prefetch (inputs only)
    float u_j = 0.f, gb_j = 0.f, ratio_in = 0.f;
    if (threadIdx.x < 64) {
        u_j      = u[j];
        gb_j     = g_bar[j];
        ratio_in = ratio[0];
    }

    cudaGridDependencySynchronize();   // K1's g_part now visible

    float a0 = 0.f, a1 = 0.f, a2 = 0.f, a3 = 0.f;
#pragma unroll
    for (int s = 0; s < 64; s += 4) {
        a0 += g_part[(size_t)(s0 + s + 0) * N_OUT + col];
        a1 += g_part[(size_t)(s0 + s + 1) * N_OUT + col];
        a2 += g_part[(size_t)(s0 + s + 2) * N_OUT + col];
        a3 += g_part[(size_t)(s0 + s + 3) * N_OUT + col];
    }
    sums[k][c] = (a0 + a1) + (a2 + a3);
    __syncthreads();

    if (threadIdx.x < 64) {
        const float u_pre = fmaf(SIG_TAU, u_j,
            ((sums[0][threadIdx.x] + sums[1][threadIdx.x]) +
             (sums[2][threadIdx.x] + sums[3][threadIdx.x])));

        const float spike = (u_pre >= 1.0f) ? 1.0f : 0.0f;
        const float t  = fmaf(10.0f, fabsf(u_pre - 1.0f), 1.0f);
        const float sg = 1.0f / (t * t);

        g_sg[j]  = sg;
        out_s[j] = spike;
        out_u[j] = u_pre - spike;          // soft reset (V_TH = 1)

        const float r0        = SIG_TAU * ratio_in;
        const float ratio_new = r0 + 1.0f;
        const float r         = r0 / ratio_new;
        // ds_du_prev / sig_tau == sg
        out_gbar[j] = fmaf(r, gb_j, (1.0f - r) * sg);

        if (j == 0) out_ratio[0] = ratio_new;
    }
}

// ---------------------------------------------------------------------------
// K3: fused E/R update, float4, 1 per thread (measured optimum: 82% DRAM).
// PDL secondary: prefetch E/R_hat/x (input-only, no hazard) before waiting
// on K2; read g_sg after. R_new = sig*R_hat + sg*E_new.
// grid 32768, block 256.
// ---------------------------------------------------------------------------
__global__ void __launch_bounds__(256)
otpe_big_elem(const float4* __restrict__ E,
              const float4* __restrict__ R,
              const float*  __restrict__ x,
              float4* __restrict__ Eo,
              float4* __restrict__ Ro) {
    const long long v = (long long)blockIdx.x * 256 + threadIdx.x;
    const int row  = (int)(v >> 10);        // 1024 float4 per row
    const int colv = (int)(v & 1023);

    // dependency-free prefetch (inputs only)
    const float  xi = __ldg(&x[row]);
    const float4 e  = E[v];
    const float4 rr = R[v];

    cudaGridDependencySynchronize();   // K2's g_sg now visible

    const float4 sg4 = reinterpret_cast<const float4*>(g_sg)[colv];

    float4 eo, ro;
    eo.x = fmaf(SIG_TAU, e.x, xi);
    eo.y = fmaf(SIG_TAU, e.y, xi);
    eo.z = fmaf(SIG_TAU, e.z, xi);
    eo.w = fmaf(SIG_TAU, e.w, xi);

    ro.x = fmaf(sg4.x, eo.x, SIG_TAU * rr.x);
    ro.y = fmaf(sg4.y, eo.y, SIG_TAU * rr.y);
    ro.z = fmaf(sg4.z, eo.z, SIG_TAU * rr.z);
    ro.w = fmaf(sg4.w, eo.w, SIG_TAU * rr.w);

    Eo[v] = eo;
    Ro[v] = ro;
}

// ---------------------------------------------------------------------------
extern "C" void kernel_launch(void* const* d_in, const int* in_sizes, int n_in,
                              void* d_out, int out_size) {
    const float* x     = (const float*)d_in[0];
    const float* W     = (const float*)d_in[1];
    const float* u     = (const float*)d_in[2];
    const float* E     = (const float*)d_in[3];
    const float* R     = (const float*)d_in[4];
    const float* g_bar = (const float*)d_in[5];
    const float* ratio = (const float*)d_in[6];

    float* out       = (float*)d_out;
    float* out_s     = out;
    float* out_u     = out + N_OUT;
    float* out_E     = out + 2 * N_OUT;
    float* out_R     = out_E + (size_t)N_IN * N_OUT;
    float* out_gbar  = out_R + (size_t)N_IN * N_OUT;
    float* out_ratio = out_gbar + N_OUT;

    // K1: normal launch
    otpe_gemv_partial<<<dim3(N_OUTV / 256, NSPLIT), 256>>>((const float4*)W, x);

    // K2, K3: programmatic dependent launches with implicit completion
    // triggers (every early-trigger variant measured slower).
    cudaLaunchAttribute pdl[1];
    pdl[0].id = cudaLaunchAttributeProgrammaticStreamSerialization;
    pdl[0].val.programmaticStreamSerializationAllowed = 1;

    {
        cudaLaunchConfig_t cfg = {};
        cfg.gridDim  = dim3(N_OUT / 64);
        cfg.blockDim = dim3(256);
        cfg.stream   = 0;
        cfg.attrs    = pdl;
        cfg.numAttrs = 1;
        cudaLaunchKernelEx(&cfg, otpe_reduce_post, u, g_bar, ratio,
                           out_s, out_u, out_gbar, out_ratio);
    }
    {
        const long long nvec = (long long)N_IN * N_OUT / 4;   // 8388608
        cudaLaunchConfig_t cfg = {};
        cfg.gridDim  = dim3((unsigned)(nvec / 256));
        cfg.blockDim = dim3(256);
        cfg.stream   = 0;
        cfg.attrs    = pdl;
        cfg.numAttrs = 1;
        cudaLaunchKernelEx(&cfg, otpe_big_elem,
                           (const float4*)E, (const float4*)R, x,
                           (float4*)out_E, (float4*)out_R);
    }
}

// round 16
// speedup vs baseline: 1.1873x; 1.0024x over previous
#include <cuda_runtime.h>

// ---------------------------------------------------------------------------
// OTPE single timestep (R8 structure; K1 pipeline depth 8->6 so the whole
// 1024-block GEMV grid is resident in ONE wave: smem 33KB->24.6KB lifts
// blocks/SM from 6 (smem-capped, 888 resident => 136-block tail) to 8
// (warp-capped, 1184 >= 1024).
// Inputs: x[8192], W[8192,4096], u[4096], E[8192,4096], R_hat[8192,4096],
//         g_bar[4096], ratio[1]
// Output: s, u_new, E_new, R_new, g_bar_new, ratio_new
// ---------------------------------------------------------------------------

#define N_IN   8192
#define N_OUT  4096
#define N_OUTV (N_OUT / 4)               // 1024 float4 per row
// sigmoid(2.0) in fp32
#define SIG_TAU 0.88079707797788231f

#define NSPLIT 256
#define ROWS_PER_SPLIT (N_IN / NSPLIT)     // 32

#define GEMV_STAGES 6                      // was 8; see header comment

// scratch (device globals; no allocation allowed)
__device__ __align__(16) float g_part[NSPLIT * N_OUT];    // 4 MB
__device__ __align__(16) float g_sg[N_OUT];

// ---------------------------------------------------------------------------
// K1: split-K GEMV via cp.async (LDGSTS .cg) 6-stage pipeline.
// grid (4, 256) = 1024 blocks, block 256, ~24.6KB smem -> 8 blocks/SM.
// Thread t stages and consumes only its own float4 column -> no
// __syncthreads in the mainloop. Loop fully unrolled; r % 6 is compile-time.
// ---------------------------------------------------------------------------
__global__ void __launch_bounds__(256)
otpe_gemv_partial(const float4* __restrict__ W4, const float* __restrict__ x) {
    __shared__ __align__(16) float4 tile[GEMV_STAGES][256];
    __shared__ float sx[ROWS_PER_SPLIT];

    const int t     = threadIdx.x;
    const int split = blockIdx.y;
    const int r0    = split * ROWS_PER_SPLIT;
    const int colv  = blockIdx.x * 256 + t;

    if (t < ROWS_PER_SPLIT)
        sx[t] = x[r0 + t];
    __syncthreads();

    const float4* Wg = W4 + (size_t)r0 * N_OUTV + colv;

#pragma unroll
    for (int s = 0; s < GEMV_STAGES; ++s) {
        unsigned dst = (unsigned)__cvta_generic_to_shared(&tile[s][t]);
        asm volatile("cp.async.cg.shared.global [%0], [%1], 16;\n"
                     :: "r"(dst), "l"(Wg + (size_t)s * N_OUTV));
        asm volatile("cp.async.commit_group;\n");
    }

    float4 A = make_float4(0.f, 0.f, 0.f, 0.f);
#pragma unroll
    for (int r = 0; r < ROWS_PER_SPLIT; ++r) {
        // allow <= STAGES-1 pending groups -> group for slot r%STAGES landed
        asm volatile("cp.async.wait_group %0;\n" :: "n"(GEMV_STAGES - 1) : "memory");
        const float4 w  = tile[r % GEMV_STAGES][t];
        const float  xr = sx[r];
        A.x = fmaf(xr, w.x, A.x);
        A.y = fmaf(xr, w.y, A.y);
        A.z = fmaf(xr, w.z, A.z);
        A.w = fmaf(xr, w.w, A.w);

        const int rn = r + GEMV_STAGES;
        if (rn < ROWS_PER_SPLIT) {
            unsigned dst = (unsigned)__cvta_generic_to_shared(
                &tile[r % GEMV_STAGES][t]);
            asm volatile("cp.async.cg.shared.global [%0], [%1], 16;\n"
                         :: "r"(dst), "l"(Wg + (size_t)rn * N_OUTV));
        }
        asm volatile("cp.async.commit_group;\n");
    }

    reinterpret_cast<float4*>(g_part)[(size_t)split * N_OUTV + colv] = A;
}

// ---------------------------------------------------------------------------
// K2: fused reduce (256 splits) + per-column post. grid 64, block 256.
// PDL secondary: prefetch u/g_bar/ratio, THEN wait on K1, THEN read g_part.
// Fixed-order smem combine keeps the reduction deterministic.
// ---------------------------------------------------------------------------
__global__ void __launch_bounds__(256)
otpe_reduce_post(const float* __restrict__ u,
                 const float* __restrict__ g_bar,
                 const float* __restrict__ ratio,
                 float* __restrict__ out_s,
                 float* __restrict__ out_u,
                 float* __restrict__ out_gbar,
                 float* __restrict__ out_ratio) {
    __shared__ float sums[4][64];

    const int c   = threadIdx.x & 63;        // column within block
    const int k   = threadIdx.x >> 6;        // split group 0..3
    const int col = blockIdx.x * 64 + c;
    const int s0  = k * 64;
    const int j   = blockIdx.x * 64 + threadIdx.x;   // valid if tid<64

    // dependency-free prefetch (inputs only)
    float u_j = 0.f, gb_j = 0.f, ratio_in = 0.f;
    if (threadIdx.x < 64) {
        u_j      = u[j];
        gb_j     = g_bar[j];
        ratio_in = ratio[0];
    }

    cudaGridDependencySynchronize();   // K1's g_part now visible

    float a0 = 0.f, a1 = 0.f, a2 = 0.f, a3 = 0.f;
#pragma unroll
    for (int s = 0; s < 64; s += 4) {
        a0 += g_part[(size_t)(s0 + s + 0) * N_OUT + col];
        a1 += g_part[(size_t)(s0 + s + 1) * N_OUT + col];
        a2 += g_part[(size_t)(s0 + s + 2) * N_OUT + col];
        a3 += g_part[(size_t)(s0 + s + 3) * N_OUT + col];
    }
    sums[k][c] = (a0 + a1) + (a2 + a3);
    __syncthreads();

    if (threadIdx.x < 64) {
        const float u_pre = fmaf(SIG_TAU, u_j,
            ((sums[0][threadIdx.x] + sums[1][threadIdx.x]) +
             (sums[2][threadIdx.x] + sums[3][threadIdx.x])));

        const float spike = (u_pre >= 1.0f) ? 1.0f : 0.0f;
        const float t  = fmaf(10.0f, fabsf(u_pre - 1.0f), 1.0f);
        const float sg = 1.0f / (t * t);

        g_sg[j]  = sg;
        out_s[j] = spike;
        out_u[j] = u_pre - spike;          // soft reset (V_TH = 1)

        const float r0        = SIG_TAU * ratio_in;
        const float ratio_new = r0 + 1.0f;
        const float r         = r0 / ratio_new;
        // ds_du_prev / sig_tau == sg
        out_gbar[j] = fmaf(r, gb_j, (1.0f - r) * sg);

        if (j == 0) out_ratio[0] = ratio_new;
    }
}

// ---------------------------------------------------------------------------
// K3: fused E/R update, float4, 1 per thread (measured optimum: 82% DRAM).
// PDL secondary: prefetch E/R_hat/x (input-only, no hazard) before waiting
// on K2; read g_sg after. R_new = sig*R_hat + sg*E_new.
// grid 32768, block 256. Byte-identical to R8.
// ---------------------------------------------------------------------------
__global__ void __launch_bounds__(256)
otpe_big_elem(const float4* __restrict__ E,
              const float4* __restrict__ R,
              const float*  __restrict__ x,
              float4* __restrict__ Eo,
              float4* __restrict__ Ro) {
    const long long v = (long long)blockIdx.x * 256 + threadIdx.x;
    const int row  = (int)(v >> 10);        // 1024 float4 per row
    const int colv = (int)(v & 1023);

    // dependency-free prefetch (inputs only)
    const float  xi = __ldg(&x[row]);
    const float4 e  = E[v];
    const float4 rr = R[v];

    cudaGridDependencySynchronize();   // K2's g_sg now visible

    const float4 sg4 = reinterpret_cast<const float4*>(g_sg)[colv];

    float4 eo, ro;
    eo.x = fmaf(SIG_TAU, e.x, xi);
    eo.y = fmaf(SIG_TAU, e.y, xi);
    eo.z = fmaf(SIG_TAU, e.z, xi);
    eo.w = fmaf(SIG_TAU, e.w, xi);

    ro.x = fmaf(sg4.x, eo.x, SIG_TAU * rr.x);
    ro.y = fmaf(sg4.y, eo.y, SIG_TAU * rr.y);
    ro.z = fmaf(sg4.z, eo.z, SIG_TAU * rr.z);
    ro.w = fmaf(sg4.w, eo.w, SIG_TAU * rr.w);

    Eo[v] = eo;
    Ro[v] = ro;
}

// ---------------------------------------------------------------------------
extern "C" void kernel_launch(void* const* d_in, const int* in_sizes, int n_in,
                              void* d_out, int out_size) {
    const float* x     = (const float*)d_in[0];
    const float* W     = (const float*)d_in[1];
    const float* u     = (const float*)d_in[2];
    const float* E     = (const float*)d_in[3];
    const float* R     = (const float*)d_in[4];
    const float* g_bar = (const float*)d_in[5];
    const float* ratio = (const float*)d_in[6];

    float* out       = (float*)d_out;
    float* out_s     = out;
    float* out_u     = out + N_OUT;
    float* out_E     = out + 2 * N_OUT;
    float* out_R     = out_E + (size_t)N_IN * N_OUT;
    float* out_gbar  = out_R + (size_t)N_IN * N_OUT;
    float* out_ratio = out_gbar + N_OUT;

    // K1: normal launch
    otpe_gemv_partial<<<dim3(N_OUTV / 256, NSPLIT), 256>>>((const float4*)W, x);

    // K2, K3: programmatic dependent launches with implicit completion
    // triggers (every early-trigger variant measured slower).
    cudaLaunchAttribute pdl[1];
    pdl[0].id = cudaLaunchAttributeProgrammaticStreamSerialization;
    pdl[0].val.programmaticStreamSerializationAllowed = 1;

    {
        cudaLaunchConfig_t cfg = {};
        cfg.gridDim  = dim3(N_OUT / 64);
        cfg.blockDim = dim3(256);
        cfg.stream   = 0;
        cfg.attrs    = pdl;
        cfg.numAttrs = 1;
        cudaLaunchKernelEx(&cfg, otpe_reduce_post, u, g_bar, ratio,
                           out_s, out_u, out_gbar, out_ratio);
    }
    {
        const long long nvec = (long long)N_IN * N_OUT / 4;   // 8388608
        cudaLaunchConfig_t cfg = {};
        cfg.gridDim  = dim3((unsigned)(nvec / 256));
        cfg.blockDim = dim3(256);
        cfg.stream   = 0;
        cfg.attrs    = pdl;
        cfg.numAttrs = 1;
        cudaLaunchKernelEx(&cfg, otpe_big_elem,
                           (const float4*)E, (const float4*)R, x,
                           (float4*)out_E, (float4*)out_R);
    }
}